// round 14
// baseline (speedup 1.0000x reference)
#include <cuda_runtime.h>
#include <cuda_bf16.h>
#include <cstdint>

#define BATCH 4
#define VOX   4096
#define DIM   256
#define HIDN  64
#define KNN_N 10
#define TOPK_N 4
#define GTOT  (BATCH*VOX)   // 16384

// ---------------- device scratch (float units) ----------------
#define OFF_A    0
#define OFF_B    1048576
#define OFF_Q    2097152
#define OFF_K    6291456
#define OFF_V    10485760
#define OFF_CTXH 14680064              // 16384*256 halves
#define OFF_CTXL 16777216
#define OFF_KNN  18874368              // 16384*10 ints
#define OFF_TOKH 19038208              // 16384*256 halves
#define OFF_TOKL 21135360
#define OFF_WTH  23232512              // 4*256*256 halves (transposed W's)
#define OFF_WTL  23363584
#define BUF_TOTAL 23494656

static __device__ float g_buf[BUF_TOTAL];

// ---------------- cp.async / ldmatrix helpers ----------------
__device__ __forceinline__ uint32_t smem_u32(const void* p) {
    return (uint32_t)__cvta_generic_to_shared(p);
}
__device__ __forceinline__ void cp16(uint32_t dst, const void* src) {
    asm volatile("cp.async.cg.shared.global [%0], [%1], 16;\n" :: "r"(dst), "l"(src));
}
__device__ __forceinline__ void cp_commit() {
    asm volatile("cp.async.commit_group;\n" ::: "memory");
}
template<int N> __device__ __forceinline__ void cp_wait() {
    asm volatile("cp.async.wait_group %0;\n" :: "n"(N) : "memory");
}
__device__ __forceinline__ void ldm_x4(uint32_t& r0, uint32_t& r1, uint32_t& r2,
                                       uint32_t& r3, uint32_t addr) {
    asm volatile("ldmatrix.sync.aligned.m8n8.x4.shared.b16 {%0,%1,%2,%3}, [%4];"
        : "=r"(r0), "=r"(r1), "=r"(r2), "=r"(r3) : "r"(addr));
}

// ---------------- convert: tok -> split bf16 ----------------
__global__ void __launch_bounds__(256) convert_tok_kernel(
        const float* __restrict__ tok,
        __nv_bfloat16* __restrict__ tokh, __nv_bfloat16* __restrict__ tokl) {
    const int idx = blockIdx.x * 256 + threadIdx.x;    // float4 index
    const int m = idx >> 6;
    const int c = (idx & 63) * 4;
    float4 v = *(const float4*)(tok + (size_t)m * 256 + c);
    __nv_bfloat16* ph = tokh + (size_t)m * 256 + c;
    __nv_bfloat16* pl = tokl + (size_t)m * 256 + c;
    float vv[4] = {v.x, v.y, v.z, v.w};
#pragma unroll
    for (int q = 0; q < 4; q++) {
        __nv_bfloat16 h = __float2bfloat16(vv[q]);
        ph[q] = h;
        pl[q] = __float2bfloat16(vv[q] - __bfloat162float(h));
    }
}

// ---------------- convert: two W's -> transposed split bf16 ----------------
__global__ void __launch_bounds__(256) convert_w_kernel(
        const float* __restrict__ Wa, const float* __restrict__ Wb,
        __nv_bfloat16* __restrict__ oh_base, __nv_bfloat16* __restrict__ ol_base) {
    const int elem = blockIdx.x * 1024 + threadIdx.x * 4;
    const int mat = elem >> 16;            // 0 or 1
    const int rem = elem & 65535;
    const int n = rem >> 8;
    const int k = rem & 255;
    const float* Wm = mat ? Wb : Wa;
    __nv_bfloat16* oh = oh_base + (size_t)mat * 65536 + (size_t)n * 256 + k;
    __nv_bfloat16* ol = ol_base + (size_t)mat * 65536 + (size_t)n * 256 + k;
#pragma unroll
    for (int q = 0; q < 4; q++) {
        float v = Wm[(size_t)(k + q) * 256 + n];
        __nv_bfloat16 h = __float2bfloat16(v);
        oh[q] = h;
        ol[q] = __float2bfloat16(v - __bfloat162float(h));
    }
}

// ---------------- KNN kernel v6 (passing R9/R11, unchanged) ----------------
#define KCHUNK 1024
#define FULLM 0xffffffffu

#define KNN_EVENTS(e, v, iv, tau)                                          \
    {                                                                      \
        unsigned mm = __ballot_sync(FULLM, (e) < (tau));                   \
        while (mm) {                                                       \
            const int s = __ffs(mm) - 1; mm &= mm - 1;  /* ascending j */  \
            const float bd = __shfl_sync(FULLM, (e), s);                   \
            const int   bjj = jj - lane + s;                               \
            if (bd < (tau)) {  /* tau tightens within batch */             \
                const unsigned bal = __ballot_sync(FULLM, bd < (v));       \
                const int pp = __ffs(bal) - 1;                             \
                const float pv = __shfl_up_sync(FULLM, (v), 1);            \
                const int   pi = __shfl_up_sync(FULLM, (iv), 1);           \
                if (lane > pp)  { (v) = pv; (iv) = pi; }                   \
                if (lane == pp) { (v) = bd; (iv) = bjj; }                  \
                (tau) = __shfl_sync(FULLM, (v), 9);                        \
            }                                                              \
        }                                                                  \
    }

__global__ void __launch_bounds__(256) knn_kernel(const float* __restrict__ coords,
                                                  int* __restrict__ knn_out) {
    __shared__ float4 sp[KCHUNK];
    const int b = blockIdx.y;
    const float* coo = coords + (size_t)b * VOX * 3;
    const int warp = threadIdx.x >> 5;
    const int lane = threadIdx.x & 31;

    const int i0 = blockIdx.x * 16 + warp * 2;
    const float x0 = coo[3*i0+0], y0 = coo[3*i0+1], z0 = coo[3*i0+2];
    const float x1 = coo[3*i0+3], y1 = coo[3*i0+4], z1 = coo[3*i0+5];
    const float sq0 = x0*x0 + y0*y0 + z0*z0;
    const float sq1 = x1*x1 + y1*y1 + z1*z1;

    float v0 = 1e30f, v1 = 1e30f;
    int  iv0 = 0x7fffffff, iv1 = 0x7fffffff;
    float tau0 = 1e30f, tau1 = 1e30f;

    for (int c = 0; c < VOX / KCHUNK; c++) {
        __syncthreads();
        for (int j = threadIdx.x; j < KCHUNK; j += 256) {
            const int jj = c * KCHUNK + j;
            const float xx = coo[3*jj], yy = coo[3*jj+1], zz = coo[3*jj+2];
            sp[j] = make_float4(xx, yy, zz, xx*xx + yy*yy + zz*zz);
        }
        __syncthreads();

        const int jbase = c * KCHUNK;
        for (int j = lane; j < KCHUNK; j += 32) {
            const float4 p = sp[j];
            const int jj = jbase + j;
            float e0 = sq0 + p.w - 2.0f*(x0*p.x + y0*p.y + z0*p.z);
            float e1 = sq1 + p.w - 2.0f*(x1*p.x + y1*p.y + z1*p.z);
            if (jj == i0)     e0 = 1e30f;
            if (jj == i0 + 1) e1 = 1e30f;
            KNN_EVENTS(e0, v0, iv0, tau0)
            KNN_EVENTS(e1, v1, iv1, tau1)
        }
    }

    if (lane < KNN_N) {
        knn_out[((b << 12) + i0 + 0) * KNN_N + lane] = iv0;
        knn_out[((b << 12) + i0 + 1) * KNN_N + lane] = iv1;
    }
}

// ---------------- fp32 GEMM body (selection path; dynamic smem) ----------------
__device__ void gemm_tile_f32(const float* __restrict__ A,
        const float* __restrict__ W, const float* __restrict__ bias,
        float* __restrict__ C, int N, int ldw, int m0, int n0, char* smem) {
    float* As = (float*)smem;        // [2][16][132]
    float* Bs = As + 2*16*132;       // [2][16][64]
#define ASX(buf,k,m) As[((buf)*16 + (k))*132 + (m)]
#define BSX(buf,k,n) Bs[((buf)*16 + (k))*64 + (n)]

    const int t  = threadIdx.x;
    const int tx = t & 15;
    const int ty = t >> 4;
    const int kq = (t & 3) * 4;
    const int ma = t >> 2;
    const int kb = t >> 4;
    const int nb = (t & 15) * 4;

    const float* Ab = A + (size_t)m0 * 256;

    float4 ra0 = *(const float4*)(Ab + (size_t)ma * 256 + kq);
    float4 ra1 = *(const float4*)(Ab + (size_t)(ma + 64) * 256 + kq);
    float4 rb  = *(const float4*)(W + (size_t)kb * ldw + n0 + nb);

    float acc[8][4];
#pragma unroll
    for (int i = 0; i < 8; i++)
#pragma unroll
        for (int j = 0; j < 4; j++) acc[i][j] = 0.0f;

    ASX(0,kq+0,ma) = ra0.x; ASX(0,kq+1,ma) = ra0.y; ASX(0,kq+2,ma) = ra0.z; ASX(0,kq+3,ma) = ra0.w;
    ASX(0,kq+0,ma+64) = ra1.x; ASX(0,kq+1,ma+64) = ra1.y; ASX(0,kq+2,ma+64) = ra1.z; ASX(0,kq+3,ma+64) = ra1.w;
    *(float4*)&BSX(0,kb,nb) = rb;
    __syncthreads();

    int cur = 0;
#pragma unroll
    for (int k0 = 0; k0 < 256; k0 += 16) {
        const bool more = (k0 + 16) < 256;
        if (more) {
            ra0 = *(const float4*)(Ab + (size_t)ma * 256 + k0 + 16 + kq);
            ra1 = *(const float4*)(Ab + (size_t)(ma + 64) * 256 + k0 + 16 + kq);
            rb  = *(const float4*)(W + (size_t)(k0 + 16 + kb) * ldw + n0 + nb);
        }
#pragma unroll
        for (int k = 0; k < 16; k++) {
            float ra[8], rbv[4];
            float4 a0 = *(const float4*)&ASX(cur,k,ty*8);
            float4 a1 = *(const float4*)&ASX(cur,k,ty*8+4);
            ra[0]=a0.x; ra[1]=a0.y; ra[2]=a0.z; ra[3]=a0.w;
            ra[4]=a1.x; ra[5]=a1.y; ra[6]=a1.z; ra[7]=a1.w;
            float4 b4 = *(const float4*)&BSX(cur,k,tx*4);
            rbv[0]=b4.x; rbv[1]=b4.y; rbv[2]=b4.z; rbv[3]=b4.w;
#pragma unroll
            for (int i = 0; i < 8; i++)
#pragma unroll
                for (int j = 0; j < 4; j++)
                    acc[i][j] += ra[i] * rbv[j];
        }
        if (more) {
            const int nx = cur ^ 1;
            ASX(nx,kq+0,ma) = ra0.x; ASX(nx,kq+1,ma) = ra0.y; ASX(nx,kq+2,ma) = ra0.z; ASX(nx,kq+3,ma) = ra0.w;
            ASX(nx,kq+0,ma+64) = ra1.x; ASX(nx,kq+1,ma+64) = ra1.y; ASX(nx,kq+2,ma+64) = ra1.z; ASX(nx,kq+3,ma+64) = ra1.w;
            *(float4*)&BSX(nx,kb,nb) = rb;
        }
        __syncthreads();
        cur ^= 1;
    }

    float4 bv = make_float4(0.f, 0.f, 0.f, 0.f);
    if (bias) bv = *(const float4*)(bias + n0 + tx*4);
#pragma unroll
    for (int i = 0; i < 8; i++) {
        const int row = m0 + ty*8 + i;
        float4 o;
        o.x = acc[i][0] + bv.x;
        o.y = acc[i][1] + bv.y;
        o.z = acc[i][2] + bv.z;
        o.w = acc[i][3] + bv.w;
        *(float4*)(C + (size_t)row * N + n0 + tx*4) = o;
    }
#undef ASX
#undef BSX
}

// ---------------- split-bf16 tensor-core GEMM v4: cp.async + ldmatrix ----------------
__device__ __forceinline__ void mma_bf16(float* c, const uint32_t* a, const uint32_t* b) {
    asm volatile(
        "mma.sync.aligned.m16n8k16.row.col.f32.bf16.bf16.f32 "
        "{%0,%1,%2,%3}, {%4,%5,%6,%7}, {%8,%9}, {%0,%1,%2,%3};\n"
        : "+f"(c[0]), "+f"(c[1]), "+f"(c[2]), "+f"(c[3])
        : "r"(a[0]), "r"(a[1]), "r"(a[2]), "r"(a[3]), "r"(b[0]), "r"(b[1]));
}

#define ASTRIDE 40           // halves; 80B row stride -> conflict-free ldmatrix
#define TCBUF_H 15360        // halves per buffer: Ah 5120 | Al 5120 | Bh 2560 | Bl 2560
#define TC_SMEM_BYTES (2 * TCBUF_H * 2)   // 61440

__device__ void tc_gemm_tile_v4(
        const __nv_bfloat16* __restrict__ Ahi, const __nv_bfloat16* __restrict__ Alo,
        const __nv_bfloat16* __restrict__ Bth, const __nv_bfloat16* __restrict__ Btl,
        const float* __restrict__ bias, float* __restrict__ C, int m0, int n0,
        __nv_bfloat16* smem) {
    const int t    = threadIdx.x;
    const int warp = t >> 5;
    const int lane = t & 31;
    const int tg   = lane & 3;
    const int mw   = warp & 3;
    const int nw   = warp >> 2;

    // staging coords: 8-half (16B) segments
    const int ar = t >> 2;            // 0..63 (A rows ar, ar+64; B row ar)
    const int ao = (t & 3) * 8;

    const __nv_bfloat16* Ah_g = Ahi + (size_t)(m0 + ar) * 256 + ao;
    const __nv_bfloat16* Al_g = Alo + (size_t)(m0 + ar) * 256 + ao;
    const __nv_bfloat16* Bh_g = Bth + (size_t)(n0 + ar) * 256 + ao;
    const __nv_bfloat16* Bl_g = Btl + (size_t)(n0 + ar) * 256 + ao;

    const uint32_t smem_b = smem_u32(smem);
    const uint32_t dA0 = smem_b + (ar*ASTRIDE + ao)*2;
    const uint32_t dA1 = smem_b + ((ar+64)*ASTRIDE + ao)*2;
    const uint32_t dL0 = smem_b + (5120 + ar*ASTRIDE + ao)*2;
    const uint32_t dL1 = smem_b + (5120 + (ar+64)*ASTRIDE + ao)*2;
    const uint32_t dBh = smem_b + (10240 + ar*ASTRIDE + ao)*2;
    const uint32_t dBl = smem_b + (12800 + ar*ASTRIDE + ao)*2;

    // ldmatrix per-lane offsets (halves):
    // A frag (16x16): mi = lane>>3; row_add=(mi&1)*8, col_add=(mi>>1)*8
    const int mi = lane >> 3, rowm = lane & 7;
    const uint32_t a_off = (uint32_t)((mw*32 + (mi&1)*8 + rowm) * ASTRIDE + (mi>>1)*8) * 2;
    // B pair-of-nt (16n x 16k): row_add=(mi>>1)*8, col_add=(mi&1)*8
    const uint32_t b_off = (uint32_t)((nw*32 + (mi>>1)*8 + rowm) * ASTRIDE + (mi&1)*8) * 2;

    float acc[2][4][4];
#pragma unroll
    for (int mt = 0; mt < 2; mt++)
#pragma unroll
        for (int nt = 0; nt < 4; nt++)
#pragma unroll
            for (int e = 0; e < 4; e++) acc[mt][nt][e] = 0.0f;

#define TC_ISSUE(buf, kk)                                                   \
    {                                                                       \
        const uint32_t bo_ = (buf) * (TCBUF_H * 2);                         \
        cp16(dA0 + bo_, Ah_g + (kk));                                       \
        cp16(dA1 + bo_, Ah_g + (size_t)64*256 + (kk));                      \
        cp16(dL0 + bo_, Al_g + (kk));                                       \
        cp16(dL1 + bo_, Al_g + (size_t)64*256 + (kk));                      \
        cp16(dBh + bo_, Bh_g + (kk));                                       \
        cp16(dBl + bo_, Bl_g + (kk));                                       \
        cp_commit();                                                        \
    }

    TC_ISSUE(0, 0)
    int cur = 0;

#pragma unroll
    for (int k0 = 0; k0 < 256; k0 += 32) {
        const bool more = (k0 + 32) < 256;
        if (more) { TC_ISSUE(cur ^ 1, k0 + 32) cp_wait<1>(); }
        else      { cp_wait<0>(); }
        __syncthreads();

        const uint32_t buf = smem_b + cur * (TCBUF_H * 2);
        const uint32_t aH = buf + a_off;
        const uint32_t aL = buf + 5120*2 + a_off;
        const uint32_t bH = buf + 10240*2 + b_off;
        const uint32_t bL = buf + 12800*2 + b_off;

#pragma unroll
        for (int ks = 0; ks < 32; ks += 16) {
            const uint32_t ko = ks * 2;
            uint32_t ah[2][4], al[2][4];
#pragma unroll
            for (int mt = 0; mt < 2; mt++) {
                const uint32_t mo = mt * (16 * ASTRIDE * 2);
                ldm_x4(ah[mt][0], ah[mt][1], ah[mt][2], ah[mt][3], aH + mo + ko);
                ldm_x4(al[mt][0], al[mt][1], al[mt][2], al[mt][3], aL + mo + ko);
            }
            uint32_t bh[4][2], bl[4][2];
#pragma unroll
            for (int p = 0; p < 2; p++) {
                const uint32_t po = p * (16 * ASTRIDE * 2);
                ldm_x4(bh[2*p][0], bh[2*p][1], bh[2*p+1][0], bh[2*p+1][1], bH + po + ko);
                ldm_x4(bl[2*p][0], bl[2*p][1], bl[2*p+1][0], bl[2*p+1][1], bL + po + ko);
            }
#pragma unroll
            for (int mt = 0; mt < 2; mt++)
#pragma unroll
                for (int nt = 0; nt < 4; nt++) {
                    mma_bf16(acc[mt][nt], ah[mt], bh[nt]);
                    mma_bf16(acc[mt][nt], ah[mt], bl[nt]);
                    mma_bf16(acc[mt][nt], al[mt], bh[nt]);
                }
        }
        __syncthreads();
        cur ^= 1;
    }
#undef TC_ISSUE

#pragma unroll
    for (int nt = 0; nt < 4; nt++) {
        const int c = n0 + nw*32 + nt*8 + 2*tg;
        float bx = 0.f, by = 0.f;
        if (bias) { bx = bias[c]; by = bias[c+1]; }
#pragma unroll
        for (int mt = 0; mt < 2; mt++) {
            const int r = m0 + mw*32 + mt*16 + (lane >> 2);
            float* Cp = C + (size_t)r * 256 + c;
            Cp[0] = acc[mt][nt][0] + bx;
            Cp[1] = acc[mt][nt][1] + by;
            Cp[(size_t)8*256]     = acc[mt][nt][2] + bx;
            Cp[(size_t)8*256 + 1] = acc[mt][nt][3] + by;
        }
    }
}

// ---------------- QKV (tc) + AB (fp32) merged ----------------
__global__ void __launch_bounds__(256, 3) qkv_ab_kernel(
        const __nv_bfloat16* __restrict__ tokh, const __nv_bfloat16* __restrict__ tokl,
        const __nv_bfloat16* __restrict__ wth,  const __nv_bfloat16* __restrict__ wtl,
        const float* __restrict__ bq, const float* __restrict__ bk, const float* __restrict__ bv,
        float* __restrict__ gQ, float* __restrict__ gK, float* __restrict__ gV,
        const float* __restrict__ tok, const float* __restrict__ W1,
        const float* __restrict__ b1, float* __restrict__ gA, float* __restrict__ gB) {
    extern __shared__ __align__(16) char dynsmem[];
    const int bid = blockIdx.x;
    if (bid < 1536) {
        const int z = bid / 512;
        const int r = bid % 512;
        const float* bias = (z == 0) ? bq : (z == 1) ? bk : bv;
        float*       C    = (z == 0) ? gQ : (z == 1) ? gK : gV;
        tc_gemm_tile_v4(tokh, tokl, wth + (size_t)z * 65536, wtl + (size_t)z * 65536,
                        bias, C, (r & 127) * 128, (r >> 7) * 64,
                        (__nv_bfloat16*)dynsmem);
    } else {
        const int a = bid - 1536;           // 0..255
        const int z = a >> 7;               // 0 -> A, 1 -> B
        const float* W    = z ? (W1 + 256*HIDN) : W1;
        const float* bias = z ? nullptr : b1;
        float*       C    = z ? gB : gA;
        gemm_tile_f32(tok, W, bias, C, HIDN, HIDN, (a & 127) * 128, 0, dynsmem);
    }
}

// ---------------- O projection ----------------
__global__ void __launch_bounds__(256, 3) tc_o_kernel(
        const __nv_bfloat16* __restrict__ ctxh, const __nv_bfloat16* __restrict__ ctxl,
        const __nv_bfloat16* __restrict__ wth,  const __nv_bfloat16* __restrict__ wtl,
        const float* __restrict__ bo, float* __restrict__ out) {
    extern __shared__ __align__(16) char dynsmem[];
    tc_gemm_tile_v4(ctxh, ctxl, wth + (size_t)3 * 65536, wtl + (size_t)3 * 65536,
                    bo, out, blockIdx.x * 128, blockIdx.y * 64,
                    (__nv_bfloat16*)dynsmem);
}

// ---------------- fused score + top-4 select + attention ----------------
__global__ void score_attn_kernel(const float* __restrict__ coords,
                                  const float* __restrict__ W1,
                                  const float* __restrict__ W2,
                                  const int* __restrict__ knn,
                                  const float* __restrict__ gA,
                                  const float* __restrict__ gB,
                                  const float* __restrict__ gQ,
                                  const float* __restrict__ gK,
                                  const float* __restrict__ gV,
                                  __nv_bfloat16* __restrict__ ctxh,
                                  __nv_bfloat16* __restrict__ ctxl) {
    __shared__ float sW1c[3][64];
    __shared__ float sW2[64];
    const int t = threadIdx.x;
    if (t < 64) {
        sW2[t]     = W2[t];
        sW1c[0][t] = W1[512*64 + t];
        sW1c[1][t] = W1[513*64 + t];
        sW1c[2][t] = W1[514*64 + t];
    }
    __syncthreads();

    const int warp = t >> 5, lane = t & 31;
    const int g = blockIdx.x * 8 + warp;
    const int b = g >> 12;
    const int i = g & 4095;
    const float* coo = coords + (size_t)b * VOX * 3;
    const float xi = coo[3*i+0], yi = coo[3*i+1], zi = coo[3*i+2];

    const float a0  = gA[(size_t)g*64 + lane];
    const float a1  = gA[(size_t)g*64 + lane + 32];
    const float w2a = sW2[lane], w2b = sW2[lane + 32];
    const float c0a = sW1c[0][lane], c0b = sW1c[0][lane+32];
    const float c1a = sW1c[1][lane], c1b = sW1c[1][lane+32];
    const float c2a = sW1c[2][lane], c2b = sW1c[2][lane+32];

    float bs[TOPK_N] = {-1e30f, -1e30f, -1e30f, -1e30f};
    int   bj[TOPK_N] = {0, 0, 0, 0};

#pragma unroll
    for (int nb = 0; nb < KNN_N; nb++) {
        const int j = knn[g*KNN_N + nb];
        const float rx = coo[3*j+0] - xi;
        const float ry = coo[3*j+1] - yi;
        const float rz = coo[3*j+2] - zi;
        const float* Bj = gB + ((size_t)(b << 12) + j) * 64;
        float h0 = a0 + Bj[lane]      + rx*c0a + ry*c1a + rz*c2a;
        float h1 = a1 + Bj[lane + 32] + rx*c0b + ry*c1b + rz*c2b;
        h0 = fmaxf(h0, 0.0f);
        h1 = fmaxf(h1, 0.0f);
        float p = h0 * w2a + h1 * w2b;
#pragma unroll
        for (int off = 16; off; off >>= 1) p += __shfl_xor_sync(0xffffffffu, p, off);
        float cs = p; int cj = j;
#pragma unroll
        for (int k = 0; k < TOPK_N; k++) {
            const bool better = cs > bs[k];
            const float ts = better ? bs[k] : cs;
            const int   tj = better ? bj[k] : cj;
            bs[k] = better ? cs : bs[k];
            bj[k] = better ? cj : bj[k];
            cs = ts; cj = tj;
        }
    }

    const size_t base = (size_t)g * DIM + lane * 8;
    const float4 q0 = *(const float4*)(gQ + base);
    const float4 q1 = *(const float4*)(gQ + base + 4);

    float att[TOPK_N];
#pragma unroll
    for (int s = 0; s < TOPK_N; s++) {
        const size_t jb = ((size_t)(b << 12) + bj[s]) * DIM + lane * 8;
        const float4* Kp = (const float4*)(gK + jb);
        const float4 k0 = Kp[0], k1 = Kp[1];
        float p = q0.x*k0.x + q0.y*k0.y + q0.z*k0.z + q0.w*k0.w
                + q1.x*k1.x + q1.y*k1.y + q1.z*k1.z + q1.w*k1.w;
        p += __shfl_xor_sync(0xffffffffu, p, 4);
        p += __shfl_xor_sync(0xffffffffu, p, 2);
        p += __shfl_xor_sync(0xffffffffu, p, 1);
        att[s] = p * 0.125f;
    }
    float m = fmaxf(fmaxf(att[0], att[1]), fmaxf(att[2], att[3]));
    float e[TOPK_N], ssum = 0.0f;
#pragma unroll
    for (int s = 0; s < TOPK_N; s++) { e[s] = expf(att[s] - m); ssum += e[s]; }
    const float inv = 1.0f / ssum;

    float cv[8] = {0.f,0.f,0.f,0.f,0.f,0.f,0.f,0.f};
#pragma unroll
    for (int s = 0; s < TOPK_N; s++) {
        const float w = e[s] * inv;
        const size_t jb = ((size_t)(b << 12) + bj[s]) * DIM + lane * 8;
        const float4* Vp = (const float4*)(gV + jb);
        const float4 v0 = Vp[0], v1 = Vp[1];
        cv[0] += w*v0.x; cv[1] += w*v0.y; cv[2] += w*v0.z; cv[3] += w*v0.w;
        cv[4] += w*v1.x; cv[5] += w*v1.y; cv[6] += w*v1.z; cv[7] += w*v1.w;
    }
    uint32_t uh[4], ul[4];
#pragma unroll
    for (int q = 0; q < 4; q++) {
        __nv_bfloat16 h0 = __float2bfloat16(cv[2*q]);
        __nv_bfloat16 h1 = __float2bfloat16(cv[2*q+1]);
        __nv_bfloat16 l0 = __float2bfloat16(cv[2*q]   - __bfloat162float(h0));
        __nv_bfloat16 l1 = __float2bfloat16(cv[2*q+1] - __bfloat162float(h1));
        __nv_bfloat162 ph(h0, h1), pl(l0, l1);
        uh[q] = *(uint32_t*)&ph;
        ul[q] = *(uint32_t*)&pl;
    }
    *(uint4*)(ctxh + base) = make_uint4(uh[0], uh[1], uh[2], uh[3]);
    *(uint4*)(ctxl + base) = make_uint4(ul[0], ul[1], ul[2], ul[3]);
}

// ---------------- launch ----------------
extern "C" void kernel_launch(void* const* d_in, const int* in_sizes, int n_in,
                              void* d_out, int out_size) {
    const float* tok    = (const float*)d_in[0];
    const float* coords = (const float*)d_in[1];
    const float* W1 = (const float*)d_in[3];
    const float* b1 = (const float*)d_in[4];
    const float* W2 = (const float*)d_in[5];
    const float* Wq = (const float*)d_in[7];
    const float* bq = (const float*)d_in[8];
    const float* Wk = (const float*)d_in[9];
    const float* bk = (const float*)d_in[10];
    const float* Wv = (const float*)d_in[11];
    const float* bv = (const float*)d_in[12];
    const float* Wo = (const float*)d_in[13];
    const float* bo = (const float*)d_in[14];
    float* out = (float*)d_out;

    void* bufp = nullptr;
    cudaGetSymbolAddress(&bufp, g_buf);
    float* buf = (float*)bufp;
    float* gA   = buf + OFF_A;
    float* gB   = buf + OFF_B;
    float* gQ   = buf + OFF_Q;
    float* gK   = buf + OFF_K;
    float* gV   = buf + OFF_V;
    int*   gknn = (int*)(buf + OFF_KNN);
    __nv_bfloat16* ctxh = (__nv_bfloat16*)(buf + OFF_CTXH);
    __nv_bfloat16* ctxl = (__nv_bfloat16*)(buf + OFF_CTXL);
    __nv_bfloat16* tokh = (__nv_bfloat16*)(buf + OFF_TOKH);
    __nv_bfloat16* tokl = (__nv_bfloat16*)(buf + OFF_TOKL);
    __nv_bfloat16* wth  = (__nv_bfloat16*)(buf + OFF_WTH);
    __nv_bfloat16* wtl  = (__nv_bfloat16*)(buf + OFF_WTL);

    cudaFuncSetAttribute(qkv_ab_kernel, cudaFuncAttributeMaxDynamicSharedMemorySize, TC_SMEM_BYTES);
    cudaFuncSetAttribute(tc_o_kernel,   cudaFuncAttributeMaxDynamicSharedMemorySize, TC_SMEM_BYTES);

    // #0..#2: split-convert
    convert_tok_kernel<<<4096, 256>>>(tok, tokh, tokl);
    convert_w_kernel<<<128, 256>>>(Wq, Wk, wth, wtl);
    convert_w_kernel<<<128, 256>>>(Wv, Wo, wth + 2*65536, wtl + 2*65536);
    // #3: QKV (tc, cp.async + ldmatrix) + AB (fp32) merged  <-- ncu capture slot
    qkv_ab_kernel<<<1792, 256, TC_SMEM_BYTES>>>(tokh, tokl, wth, wtl,
                                                bq, bk, bv, gQ, gK, gV,
                                                tok, W1, b1, gA, gB);
    // #4: knn v6
    knn_kernel<<<dim3(256, 4), 256>>>(coords, gknn);
    // #5: fused score + select + attention (writes split ctx)
    score_attn_kernel<<<GTOT/8, 256>>>(coords, W1, W2, gknn, gA, gB, gQ, gK, gV, ctxh, ctxl);
    // #6: output projection
    tc_o_kernel<<<dim3(GTOT/128, DIM/64), 256, TC_SMEM_BYTES>>>(ctxh, ctxl, wth, wtl, bo, out);
}

// round 15
// speedup vs baseline: 1.4786x; 1.4786x over previous
#include <cuda_runtime.h>
#include <cuda_bf16.h>
#include <cstdint>

#define BATCH 4
#define VOX   4096
#define DIM   256
#define HIDN  64
#define KNN_N 10
#define TOPK_N 4
#define GTOT  (BATCH*VOX)   // 16384

// ---------------- device scratch (float units) ----------------
#define OFF_A    0
#define OFF_B    1048576
#define OFF_Q    2097152
#define OFF_K    6291456
#define OFF_V    10485760
#define OFF_CTXH 14680064              // 16384*256 halves
#define OFF_CTXL 16777216
#define OFF_KNN  18874368              // 16384*10 ints
#define OFF_TOKH 19038208              // 16384*256 halves
#define OFF_TOKL 21135360
#define OFF_WTH  23232512              // 4*256*256 halves (transposed W's)
#define OFF_WTL  23363584
#define BUF_TOTAL 23494656

static __device__ float g_buf[BUF_TOTAL];

// ---------------- cp.async helpers ----------------
__device__ __forceinline__ uint32_t smem_u32(const void* p) {
    return (uint32_t)__cvta_generic_to_shared(p);
}
__device__ __forceinline__ void cp16(uint32_t dst, const void* src) {
    asm volatile("cp.async.cg.shared.global [%0], [%1], 16;\n" :: "r"(dst), "l"(src));
}
__device__ __forceinline__ void cp_commit() {
    asm volatile("cp.async.commit_group;\n" ::: "memory");
}
template<int N> __device__ __forceinline__ void cp_wait() {
    asm volatile("cp.async.wait_group %0;\n" :: "n"(N) : "memory");
}

// ---------------- convert: tok -> split bf16 ----------------
__global__ void __launch_bounds__(256) convert_tok_kernel(
        const float* __restrict__ tok,
        __nv_bfloat16* __restrict__ tokh, __nv_bfloat16* __restrict__ tokl) {
    const int idx = blockIdx.x * 256 + threadIdx.x;    // float4 index
    const int m = idx >> 6;
    const int c = (idx & 63) * 4;
    float4 v = *(const float4*)(tok + (size_t)m * 256 + c);
    __nv_bfloat16* ph = tokh + (size_t)m * 256 + c;
    __nv_bfloat16* pl = tokl + (size_t)m * 256 + c;
    float vv[4] = {v.x, v.y, v.z, v.w};
#pragma unroll
    for (int q = 0; q < 4; q++) {
        __nv_bfloat16 h = __float2bfloat16(vv[q]);
        ph[q] = h;
        pl[q] = __float2bfloat16(vv[q] - __bfloat162float(h));
    }
}

// ---------------- convert: two W's -> transposed split bf16 ----------------
__global__ void __launch_bounds__(256) convert_w_kernel(
        const float* __restrict__ Wa, const float* __restrict__ Wb,
        __nv_bfloat16* __restrict__ oh_base, __nv_bfloat16* __restrict__ ol_base) {
    const int elem = blockIdx.x * 1024 + threadIdx.x * 4;
    const int mat = elem >> 16;            // 0 or 1
    const int rem = elem & 65535;
    const int n = rem >> 8;
    const int k = rem & 255;
    const float* Wm = mat ? Wb : Wa;
    __nv_bfloat16* oh = oh_base + (size_t)mat * 65536 + (size_t)n * 256 + k;
    __nv_bfloat16* ol = ol_base + (size_t)mat * 65536 + (size_t)n * 256 + k;
#pragma unroll
    for (int q = 0; q < 4; q++) {
        float v = Wm[(size_t)(k + q) * 256 + n];
        __nv_bfloat16 h = __float2bfloat16(v);
        oh[q] = h;
        ol[q] = __float2bfloat16(v - __bfloat162float(h));
    }
}

// ---------------- KNN kernel v6 (passing R9/R11, unchanged) ----------------
#define KCHUNK 1024
#define FULLM 0xffffffffu

#define KNN_EVENTS(e, v, iv, tau)                                          \
    {                                                                      \
        unsigned mm = __ballot_sync(FULLM, (e) < (tau));                   \
        while (mm) {                                                       \
            const int s = __ffs(mm) - 1; mm &= mm - 1;  /* ascending j */  \
            const float bd = __shfl_sync(FULLM, (e), s);                   \
            const int   bjj = jj - lane + s;                               \
            if (bd < (tau)) {  /* tau tightens within batch */             \
                const unsigned bal = __ballot_sync(FULLM, bd < (v));       \
                const int pp = __ffs(bal) - 1;                             \
                const float pv = __shfl_up_sync(FULLM, (v), 1);            \
                const int   pi = __shfl_up_sync(FULLM, (iv), 1);           \
                if (lane > pp)  { (v) = pv; (iv) = pi; }                   \
                if (lane == pp) { (v) = bd; (iv) = bjj; }                  \
                (tau) = __shfl_sync(FULLM, (v), 9);                        \
            }                                                              \
        }                                                                  \
    }

__global__ void __launch_bounds__(256) knn_kernel(const float* __restrict__ coords,
                                                  int* __restrict__ knn_out) {
    __shared__ float4 sp[KCHUNK];
    const int b = blockIdx.y;
    const float* coo = coords + (size_t)b * VOX * 3;
    const int warp = threadIdx.x >> 5;
    const int lane = threadIdx.x & 31;

    const int i0 = blockIdx.x * 16 + warp * 2;
    const float x0 = coo[3*i0+0], y0 = coo[3*i0+1], z0 = coo[3*i0+2];
    const float x1 = coo[3*i0+3], y1 = coo[3*i0+4], z1 = coo[3*i0+5];
    const float sq0 = x0*x0 + y0*y0 + z0*z0;
    const float sq1 = x1*x1 + y1*y1 + z1*z1;

    float v0 = 1e30f, v1 = 1e30f;
    int  iv0 = 0x7fffffff, iv1 = 0x7fffffff;
    float tau0 = 1e30f, tau1 = 1e30f;

    for (int c = 0; c < VOX / KCHUNK; c++) {
        __syncthreads();
        for (int j = threadIdx.x; j < KCHUNK; j += 256) {
            const int jj = c * KCHUNK + j;
            const float xx = coo[3*jj], yy = coo[3*jj+1], zz = coo[3*jj+2];
            sp[j] = make_float4(xx, yy, zz, xx*xx + yy*yy + zz*zz);
        }
        __syncthreads();

        const int jbase = c * KCHUNK;
        for (int j = lane; j < KCHUNK; j += 32) {
            const float4 p = sp[j];
            const int jj = jbase + j;
            float e0 = sq0 + p.w - 2.0f*(x0*p.x + y0*p.y + z0*p.z);
            float e1 = sq1 + p.w - 2.0f*(x1*p.x + y1*p.y + z1*p.z);
            if (jj == i0)     e0 = 1e30f;
            if (jj == i0 + 1) e1 = 1e30f;
            KNN_EVENTS(e0, v0, iv0, tau0)
            KNN_EVENTS(e1, v1, iv1, tau1)
        }
    }

    if (lane < KNN_N) {
        knn_out[((b << 12) + i0 + 0) * KNN_N + lane] = iv0;
        knn_out[((b << 12) + i0 + 1) * KNN_N + lane] = iv1;
    }
}

// ---------------- fp32 GEMM body (selection path; dynamic smem) ----------------
__device__ void gemm_tile_f32(const float* __restrict__ A,
        const float* __restrict__ W, const float* __restrict__ bias,
        float* __restrict__ C, int N, int ldw, int m0, int n0, char* smem) {
    float* As = (float*)smem;        // [2][16][132]
    float* Bs = As + 2*16*132;       // [2][16][64]
#define ASX(buf,k,m) As[((buf)*16 + (k))*132 + (m)]
#define BSX(buf,k,n) Bs[((buf)*16 + (k))*64 + (n)]

    const int t  = threadIdx.x;
    const int tx = t & 15;
    const int ty = t >> 4;
    const int kq = (t & 3) * 4;
    const int ma = t >> 2;
    const int kb = t >> 4;
    const int nb = (t & 15) * 4;

    const float* Ab = A + (size_t)m0 * 256;

    float4 ra0 = *(const float4*)(Ab + (size_t)ma * 256 + kq);
    float4 ra1 = *(const float4*)(Ab + (size_t)(ma + 64) * 256 + kq);
    float4 rb  = *(const float4*)(W + (size_t)kb * ldw + n0 + nb);

    float acc[8][4];
#pragma unroll
    for (int i = 0; i < 8; i++)
#pragma unroll
        for (int j = 0; j < 4; j++) acc[i][j] = 0.0f;

    ASX(0,kq+0,ma) = ra0.x; ASX(0,kq+1,ma) = ra0.y; ASX(0,kq+2,ma) = ra0.z; ASX(0,kq+3,ma) = ra0.w;
    ASX(0,kq+0,ma+64) = ra1.x; ASX(0,kq+1,ma+64) = ra1.y; ASX(0,kq+2,ma+64) = ra1.z; ASX(0,kq+3,ma+64) = ra1.w;
    *(float4*)&BSX(0,kb,nb) = rb;
    __syncthreads();

    int cur = 0;
#pragma unroll
    for (int k0 = 0; k0 < 256; k0 += 16) {
        const bool more = (k0 + 16) < 256;
        if (more) {
            ra0 = *(const float4*)(Ab + (size_t)ma * 256 + k0 + 16 + kq);
            ra1 = *(const float4*)(Ab + (size_t)(ma + 64) * 256 + k0 + 16 + kq);
            rb  = *(const float4*)(W + (size_t)(k0 + 16 + kb) * ldw + n0 + nb);
        }
#pragma unroll
        for (int k = 0; k < 16; k++) {
            float ra[8], rbv[4];
            float4 a0 = *(const float4*)&ASX(cur,k,ty*8);
            float4 a1 = *(const float4*)&ASX(cur,k,ty*8+4);
            ra[0]=a0.x; ra[1]=a0.y; ra[2]=a0.z; ra[3]=a0.w;
            ra[4]=a1.x; ra[5]=a1.y; ra[6]=a1.z; ra[7]=a1.w;
            float4 b4 = *(const float4*)&BSX(cur,k,tx*4);
            rbv[0]=b4.x; rbv[1]=b4.y; rbv[2]=b4.z; rbv[3]=b4.w;
#pragma unroll
            for (int i = 0; i < 8; i++)
#pragma unroll
                for (int j = 0; j < 4; j++)
                    acc[i][j] += ra[i] * rbv[j];
        }
        if (more) {
            const int nx = cur ^ 1;
            ASX(nx,kq+0,ma) = ra0.x; ASX(nx,kq+1,ma) = ra0.y; ASX(nx,kq+2,ma) = ra0.z; ASX(nx,kq+3,ma) = ra0.w;
            ASX(nx,kq+0,ma+64) = ra1.x; ASX(nx,kq+1,ma+64) = ra1.y; ASX(nx,kq+2,ma+64) = ra1.z; ASX(nx,kq+3,ma+64) = ra1.w;
            *(float4*)&BSX(nx,kb,nb) = rb;
        }
        __syncthreads();
        cur ^= 1;
    }

    float4 bv = make_float4(0.f, 0.f, 0.f, 0.f);
    if (bias) bv = *(const float4*)(bias + n0 + tx*4);
#pragma unroll
    for (int i = 0; i < 8; i++) {
        const int row = m0 + ty*8 + i;
        float4 o;
        o.x = acc[i][0] + bv.x;
        o.y = acc[i][1] + bv.y;
        o.z = acc[i][2] + bv.z;
        o.w = acc[i][3] + bv.w;
        *(float4*)(C + (size_t)row * N + n0 + tx*4) = o;
    }
#undef ASX
#undef BSX
}

// ---------------- split-bf16 tensor-core GEMM v5: term-major MMA ordering ----------------
__device__ __forceinline__ void mma_bf16(float* c, const uint32_t* a, const uint32_t* b) {
    asm volatile(
        "mma.sync.aligned.m16n8k16.row.col.f32.bf16.bf16.f32 "
        "{%0,%1,%2,%3}, {%4,%5,%6,%7}, {%8,%9}, {%0,%1,%2,%3};\n"
        : "+f"(c[0]), "+f"(c[1]), "+f"(c[2]), "+f"(c[3])
        : "r"(a[0]), "r"(a[1]), "r"(a[2]), "r"(a[3]), "r"(b[0]), "r"(b[1]));
}

#define ASTRIDE 40           // halves; 80B row stride -> conflict-free
#define TCBUF_H 15360        // halves per buffer: Ah 5120 | Al 5120 | Bh 2560 | Bl 2560
#define TC_SMEM_BYTES (2 * TCBUF_H * 2)   // 61440

__device__ void tc_gemm_tile_v5(
        const __nv_bfloat16* __restrict__ Ahi, const __nv_bfloat16* __restrict__ Alo,
        const __nv_bfloat16* __restrict__ Bth, const __nv_bfloat16* __restrict__ Btl,
        const float* __restrict__ bias, float* __restrict__ C, int m0, int n0,
        __nv_bfloat16* smem) {
    const int t    = threadIdx.x;
    const int warp = t >> 5;
    const int lane = t & 31;
    const int g    = lane >> 2;
    const int tg   = lane & 3;
    const int mw   = warp & 3;
    const int nw   = warp >> 2;

    const int ar = t >> 2;            // 0..63 (A rows ar, ar+64; B row ar)
    const int ao = (t & 3) * 8;       // 8-half segment

    const __nv_bfloat16* Ah_g = Ahi + (size_t)(m0 + ar) * 256 + ao;
    const __nv_bfloat16* Al_g = Alo + (size_t)(m0 + ar) * 256 + ao;
    const __nv_bfloat16* Bh_g = Bth + (size_t)(n0 + ar) * 256 + ao;
    const __nv_bfloat16* Bl_g = Btl + (size_t)(n0 + ar) * 256 + ao;

    const uint32_t smem_b = smem_u32(smem);
    const uint32_t dA0 = smem_b + (ar*ASTRIDE + ao)*2;
    const uint32_t dA1 = smem_b + ((ar+64)*ASTRIDE + ao)*2;
    const uint32_t dL0 = smem_b + (5120 + ar*ASTRIDE + ao)*2;
    const uint32_t dL1 = smem_b + (5120 + (ar+64)*ASTRIDE + ao)*2;
    const uint32_t dBh = smem_b + (10240 + ar*ASTRIDE + ao)*2;
    const uint32_t dBl = smem_b + (12800 + ar*ASTRIDE + ao)*2;

    float acc[2][4][4];
#pragma unroll
    for (int mt = 0; mt < 2; mt++)
#pragma unroll
        for (int nt = 0; nt < 4; nt++)
#pragma unroll
            for (int e = 0; e < 4; e++) acc[mt][nt][e] = 0.0f;

#define TC_ISSUE(buf, kk)                                                   \
    {                                                                       \
        const uint32_t bo_ = (buf) * (TCBUF_H * 2);                         \
        cp16(dA0 + bo_, Ah_g + (kk));                                       \
        cp16(dA1 + bo_, Ah_g + (size_t)64*256 + (kk));                      \
        cp16(dL0 + bo_, Al_g + (kk));                                       \
        cp16(dL1 + bo_, Al_g + (size_t)64*256 + (kk));                      \
        cp16(dBh + bo_, Bh_g + (kk));                                       \
        cp16(dBl + bo_, Bl_g + (kk));                                       \
        cp_commit();                                                        \
    }

    TC_ISSUE(0, 0)
    int cur = 0;

#pragma unroll
    for (int k0 = 0; k0 < 256; k0 += 32) {
        const bool more = (k0 + 32) < 256;
        if (more) { TC_ISSUE(cur ^ 1, k0 + 32) cp_wait<1>(); }
        else      { cp_wait<0>(); }
        __syncthreads();

        const __nv_bfloat16* Ah = smem + cur * TCBUF_H;
        const __nv_bfloat16* Al = Ah + 5120;
        const __nv_bfloat16* Bh = Ah + 10240;
        const __nv_bfloat16* Bl = Ah + 12800;

#pragma unroll
        for (int ks = 0; ks < 32; ks += 16) {
            uint32_t ah[2][4], al[2][4];
#pragma unroll
            for (int mt = 0; mt < 2; mt++) {
                const int r = mw*32 + mt*16 + g;
                ah[mt][0] = *(const uint32_t*)&Ah[r*ASTRIDE + ks + 2*tg];
                ah[mt][1] = *(const uint32_t*)&Ah[(r+8)*ASTRIDE + ks + 2*tg];
                ah[mt][2] = *(const uint32_t*)&Ah[r*ASTRIDE + ks + 8 + 2*tg];
                ah[mt][3] = *(const uint32_t*)&Ah[(r+8)*ASTRIDE + ks + 8 + 2*tg];
                al[mt][0] = *(const uint32_t*)&Al[r*ASTRIDE + ks + 2*tg];
                al[mt][1] = *(const uint32_t*)&Al[(r+8)*ASTRIDE + ks + 2*tg];
                al[mt][2] = *(const uint32_t*)&Al[r*ASTRIDE + ks + 8 + 2*tg];
                al[mt][3] = *(const uint32_t*)&Al[(r+8)*ASTRIDE + ks + 8 + 2*tg];
            }
            uint32_t bh[4][2], bl[4][2];
#pragma unroll
            for (int nt = 0; nt < 4; nt++) {
                const int n = nw*32 + nt*8 + g;
                bh[nt][0] = *(const uint32_t*)&Bh[n*ASTRIDE + ks + 2*tg];
                bh[nt][1] = *(const uint32_t*)&Bh[n*ASTRIDE + ks + 8 + 2*tg];
                bl[nt][0] = *(const uint32_t*)&Bl[n*ASTRIDE + ks + 2*tg];
                bl[nt][1] = *(const uint32_t*)&Bl[n*ASTRIDE + ks + 8 + 2*tg];
            }
            // term-major: 8 independent MMAs between successive writes to the
            // same accumulator -> acc RAW latency hidden. Per-acc order stays
            // hh, hl, lh (bit-identical numerics vs v3).
#pragma unroll
            for (int mt = 0; mt < 2; mt++)
#pragma unroll
                for (int nt = 0; nt < 4; nt++)
                    mma_bf16(acc[mt][nt], ah[mt], bh[nt]);
#pragma unroll
            for (int mt = 0; mt < 2; mt++)
#pragma unroll
                for (int nt = 0; nt < 4; nt++)
                    mma_bf16(acc[mt][nt], ah[mt], bl[nt]);
#pragma unroll
            for (int mt = 0; mt < 2; mt++)
#pragma unroll
                for (int nt = 0; nt < 4; nt++)
                    mma_bf16(acc[mt][nt], al[mt], bh[nt]);
        }
        __syncthreads();
        cur ^= 1;
    }
#undef TC_ISSUE

#pragma unroll
    for (int nt = 0; nt < 4; nt++) {
        const int c = n0 + nw*32 + nt*8 + 2*tg;
        float bx = 0.f, by = 0.f;
        if (bias) { bx = bias[c]; by = bias[c+1]; }
#pragma unroll
        for (int mt = 0; mt < 2; mt++) {
            const int r = m0 + mw*32 + mt*16 + g;
            float* Cp = C + (size_t)r * 256 + c;
            Cp[0] = acc[mt][nt][0] + bx;
            Cp[1] = acc[mt][nt][1] + by;
            Cp[(size_t)8*256]     = acc[mt][nt][2] + bx;
            Cp[(size_t)8*256 + 1] = acc[mt][nt][3] + by;
        }
    }
}

// ---------------- QKV (tc) + AB (fp32) merged — matched reg footprints ----------------
__global__ void __launch_bounds__(256, 3) qkv_ab_kernel(
        const __nv_bfloat16* __restrict__ tokh, const __nv_bfloat16* __restrict__ tokl,
        const __nv_bfloat16* __restrict__ wth,  const __nv_bfloat16* __restrict__ wtl,
        const float* __restrict__ bq, const float* __restrict__ bk, const float* __restrict__ bv,
        float* __restrict__ gQ, float* __restrict__ gK, float* __restrict__ gV,
        const float* __restrict__ tok, const float* __restrict__ W1,
        const float* __restrict__ b1, float* __restrict__ gA, float* __restrict__ gB) {
    extern __shared__ __align__(16) char dynsmem[];
    const int bid = blockIdx.x;
    if (bid < 1536) {
        const int z = bid / 512;
        const int r = bid % 512;
        const float* bias = (z == 0) ? bq : (z == 1) ? bk : bv;
        float*       C    = (z == 0) ? gQ : (z == 1) ? gK : gV;
        tc_gemm_tile_v5(tokh, tokl, wth + (size_t)z * 65536, wtl + (size_t)z * 65536,
                        bias, C, (r & 127) * 128, (r >> 7) * 64,
                        (__nv_bfloat16*)dynsmem);
    } else {
        const int a = bid - 1536;           // 0..255
        const int z = a >> 7;               // 0 -> A, 1 -> B
        const float* W    = z ? (W1 + 256*HIDN) : W1;
        const float* bias = z ? nullptr : b1;
        float*       C    = z ? gB : gA;
        gemm_tile_f32(tok, W, bias, C, HIDN, HIDN, (a & 127) * 128, 0, dynsmem);
    }
}

// ---------------- O projection ----------------
__global__ void __launch_bounds__(256, 3) tc_o_kernel(
        const __nv_bfloat16* __restrict__ ctxh, const __nv_bfloat16* __restrict__ ctxl,
        const __nv_bfloat16* __restrict__ wth,  const __nv_bfloat16* __restrict__ wtl,
        const float* __restrict__ bo, float* __restrict__ out) {
    extern __shared__ __align__(16) char dynsmem[];
    tc_gemm_tile_v5(ctxh, ctxl, wth + (size_t)3 * 65536, wtl + (size_t)3 * 65536,
                    bo, out, blockIdx.x * 128, blockIdx.y * 64,
                    (__nv_bfloat16*)dynsmem);
}

// ---------------- fused score + top-4 select + attention ----------------
__global__ void score_attn_kernel(const float* __restrict__ coords,
                                  const float* __restrict__ W1,
                                  const float* __restrict__ W2,
                                  const int* __restrict__ knn,
                                  const float* __restrict__ gA,
                                  const float* __restrict__ gB,
                                  const float* __restrict__ gQ,
                                  const float* __restrict__ gK,
                                  const float* __restrict__ gV,
                                  __nv_bfloat16* __restrict__ ctxh,
                                  __nv_bfloat16* __restrict__ ctxl) {
    __shared__ float sW1c[3][64];
    __shared__ float sW2[64];
    const int t = threadIdx.x;
    if (t < 64) {
        sW2[t]     = W2[t];
        sW1c[0][t] = W1[512*64 + t];
        sW1c[1][t] = W1[513*64 + t];
        sW1c[2][t] = W1[514*64 + t];
    }
    __syncthreads();

    const int warp = t >> 5, lane = t & 31;
    const int g = blockIdx.x * 8 + warp;
    const int b = g >> 12;
    const int i = g & 4095;
    const float* coo = coords + (size_t)b * VOX * 3;
    const float xi = coo[3*i+0], yi = coo[3*i+1], zi = coo[3*i+2];

    const float a0  = gA[(size_t)g*64 + lane];
    const float a1  = gA[(size_t)g*64 + lane + 32];
    const float w2a = sW2[lane], w2b = sW2[lane + 32];
    const float c0a = sW1c[0][lane], c0b = sW1c[0][lane+32];
    const float c1a = sW1c[1][lane], c1b = sW1c[1][lane+32];
    const float c2a = sW1c[2][lane], c2b = sW1c[2][lane+32];

    float bs[TOPK_N] = {-1e30f, -1e30f, -1e30f, -1e30f};
    int   bj[TOPK_N] = {0, 0, 0, 0};

#pragma unroll
    for (int nb = 0; nb < KNN_N; nb++) {
        const int j = knn[g*KNN_N + nb];
        const float rx = coo[3*j+0] - xi;
        const float ry = coo[3*j+1] - yi;
        const float rz = coo[3*j+2] - zi;
        const float* Bj = gB + ((size_t)(b << 12) + j) * 64;
        float h0 = a0 + Bj[lane]      + rx*c0a + ry*c1a + rz*c2a;
        float h1 = a1 + Bj[lane + 32] + rx*c0b + ry*c1b + rz*c2b;
        h0 = fmaxf(h0, 0.0f);
        h1 = fmaxf(h1, 0.0f);
        float p = h0 * w2a + h1 * w2b;
#pragma unroll
        for (int off = 16; off; off >>= 1) p += __shfl_xor_sync(0xffffffffu, p, off);
        float cs = p; int cj = j;
#pragma unroll
        for (int k = 0; k < TOPK_N; k++) {
            const bool better = cs > bs[k];
            const float ts = better ? bs[k] : cs;
            const int   tj = better ? bj[k] : cj;
            bs[k] = better ? cs : bs[k];
            bj[k] = better ? cj : bj[k];
            cs = ts; cj = tj;
        }
    }

    const size_t base = (size_t)g * DIM + lane * 8;
    const float4 q0 = *(const float4*)(gQ + base);
    const float4 q1 = *(const float4*)(gQ + base + 4);

    float att[TOPK_N];
#pragma unroll
    for (int s = 0; s < TOPK_N; s++) {
        const size_t jb = ((size_t)(b << 12) + bj[s]) * DIM + lane * 8;
        const float4* Kp = (const float4*)(gK + jb);
        const float4 k0 = Kp[0], k1 = Kp[1];
        float p = q0.x*k0.x + q0.y*k0.y + q0.z*k0.z + q0.w*k0.w
                + q1.x*k1.x + q1.y*k1.y + q1.z*k1.z + q1.w*k1.w;
        p += __shfl_xor_sync(0xffffffffu, p, 4);
        p += __shfl_xor_sync(0xffffffffu, p, 2);
        p += __shfl_xor_sync(0xffffffffu, p, 1);
        att[s] = p * 0.125f;
    }
    float m = fmaxf(fmaxf(att[0], att[1]), fmaxf(att[2], att[3]));
    float e[TOPK_N], ssum = 0.0f;
#pragma unroll
    for (int s = 0; s < TOPK_N; s++) { e[s] = expf(att[s] - m); ssum += e[s]; }
    const float inv = 1.0f / ssum;

    float cv[8] = {0.f,0.f,0.f,0.f,0.f,0.f,0.f,0.f};
#pragma unroll
    for (int s = 0; s < TOPK_N; s++) {
        const float w = e[s] * inv;
        const size_t jb = ((size_t)(b << 12) + bj[s]) * DIM + lane * 8;
        const float4* Vp = (const float4*)(gV + jb);
        const float4 v0 = Vp[0], v1 = Vp[1];
        cv[0] += w*v0.x; cv[1] += w*v0.y; cv[2] += w*v0.z; cv[3] += w*v0.w;
        cv[4] += w*v1.x; cv[5] += w*v1.y; cv[6] += w*v1.z; cv[7] += w*v1.w;
    }
    uint32_t uh[4], ul[4];
#pragma unroll
    for (int q = 0; q < 4; q++) {
        __nv_bfloat16 h0 = __float2bfloat16(cv[2*q]);
        __nv_bfloat16 h1 = __float2bfloat16(cv[2*q+1]);
        __nv_bfloat16 l0 = __float2bfloat16(cv[2*q]   - __bfloat162float(h0));
        __nv_bfloat16 l1 = __float2bfloat16(cv[2*q+1] - __bfloat162float(h1));
        __nv_bfloat162 ph(h0, h1), pl(l0, l1);
        uh[q] = *(uint32_t*)&ph;
        ul[q] = *(uint32_t*)&pl;
    }
    *(uint4*)(ctxh + base) = make_uint4(uh[0], uh[1], uh[2], uh[3]);
    *(uint4*)(ctxl + base) = make_uint4(ul[0], ul[1], ul[2], ul[3]);
}

// ---------------- launch ----------------
extern "C" void kernel_launch(void* const* d_in, const int* in_sizes, int n_in,
                              void* d_out, int out_size) {
    const float* tok    = (const float*)d_in[0];
    const float* coords = (const float*)d_in[1];
    const float* W1 = (const float*)d_in[3];
    const float* b1 = (const float*)d_in[4];
    const float* W2 = (const float*)d_in[5];
    const float* Wq = (const float*)d_in[7];
    const float* bq = (const float*)d_in[8];
    const float* Wk = (const float*)d_in[9];
    const float* bk = (const float*)d_in[10];
    const float* Wv = (const float*)d_in[11];
    const float* bv = (const float*)d_in[12];
    const float* Wo = (const float*)d_in[13];
    const float* bo = (const float*)d_in[14];
    float* out = (float*)d_out;

    void* bufp = nullptr;
    cudaGetSymbolAddress(&bufp, g_buf);
    float* buf = (float*)bufp;
    float* gA   = buf + OFF_A;
    float* gB   = buf + OFF_B;
    float* gQ   = buf + OFF_Q;
    float* gK   = buf + OFF_K;
    float* gV   = buf + OFF_V;
    int*   gknn = (int*)(buf + OFF_KNN);
    __nv_bfloat16* ctxh = (__nv_bfloat16*)(buf + OFF_CTXH);
    __nv_bfloat16* ctxl = (__nv_bfloat16*)(buf + OFF_CTXL);
    __nv_bfloat16* tokh = (__nv_bfloat16*)(buf + OFF_TOKH);
    __nv_bfloat16* tokl = (__nv_bfloat16*)(buf + OFF_TOKL);
    __nv_bfloat16* wth  = (__nv_bfloat16*)(buf + OFF_WTH);
    __nv_bfloat16* wtl  = (__nv_bfloat16*)(buf + OFF_WTL);

    cudaFuncSetAttribute(qkv_ab_kernel, cudaFuncAttributeMaxDynamicSharedMemorySize, TC_SMEM_BYTES);
    cudaFuncSetAttribute(tc_o_kernel,   cudaFuncAttributeMaxDynamicSharedMemorySize, TC_SMEM_BYTES);

    // #0..#2: split-convert
    convert_tok_kernel<<<4096, 256>>>(tok, tokh, tokl);
    convert_w_kernel<<<128, 256>>>(Wq, Wk, wth, wtl);
    convert_w_kernel<<<128, 256>>>(Wv, Wo, wth + 2*65536, wtl + 2*65536);
    // #3: QKV (tc v5, term-major) + AB (fp32) merged  <-- ncu capture slot
    qkv_ab_kernel<<<1792, 256, TC_SMEM_BYTES>>>(tokh, tokl, wth, wtl,
                                                bq, bk, bv, gQ, gK, gV,
                                                tok, W1, b1, gA, gB);
    // #4: knn v6
    knn_kernel<<<dim3(256, 4), 256>>>(coords, gknn);
    // #5: fused score + select + attention (writes split ctx)
    score_attn_kernel<<<GTOT/8, 256>>>(coords, W1, W2, gknn, gA, gB, gQ, gK, gV, ctxh, ctxl);
    // #6: output projection
    tc_o_kernel<<<dim3(GTOT/128, DIM/64), 256, TC_SMEM_BYTES>>>(ctxh, ctxl, wth, wtl, bo, out);
}

// round 17
// speedup vs baseline: 1.5004x; 1.0148x over previous
#include <cuda_runtime.h>
#include <cuda_bf16.h>
#include <cstdint>

#define BATCH 4
#define VOX   4096
#define DIM   256
#define HIDN  64
#define KNN_N 10
#define TOPK_N 4
#define GTOT  (BATCH*VOX)   // 16384

// ---------------- device scratch (float units) ----------------
#define OFF_A    0
#define OFF_B    1048576
#define OFF_Q    2097152
#define OFF_K    6291456
#define OFF_V    10485760
#define OFF_CTXH 14680064              // 16384*256 halves
#define OFF_CTXL 16777216
#define OFF_KNN  18874368              // 16384*10 ints
#define OFF_TOKH 19038208              // 16384*256 halves
#define OFF_TOKL 21135360
#define OFF_WTH  23232512              // 4*256*256 halves (transposed W's)
#define OFF_WTL  23363584
#define BUF_TOTAL 23494656

static __device__ float g_buf[BUF_TOTAL];

// ---------------- cp.async helpers ----------------
__device__ __forceinline__ uint32_t smem_u32(const void* p) {
    return (uint32_t)__cvta_generic_to_shared(p);
}
__device__ __forceinline__ void cp16(uint32_t dst, const void* src) {
    asm volatile("cp.async.cg.shared.global [%0], [%1], 16;\n" :: "r"(dst), "l"(src));
}
__device__ __forceinline__ void cp_commit() {
    asm volatile("cp.async.commit_group;\n" ::: "memory");
}
template<int N> __device__ __forceinline__ void cp_wait() {
    asm volatile("cp.async.wait_group %0;\n" :: "n"(N) : "memory");
}

// ---------------- convert: tok -> split bf16 ----------------
__global__ void __launch_bounds__(256) convert_tok_kernel(
        const float* __restrict__ tok,
        __nv_bfloat16* __restrict__ tokh, __nv_bfloat16* __restrict__ tokl) {
    const int idx = blockIdx.x * 256 + threadIdx.x;    // float4 index
    const int m = idx >> 6;
    const int c = (idx & 63) * 4;
    float4 v = *(const float4*)(tok + (size_t)m * 256 + c);
    __nv_bfloat16* ph = tokh + (size_t)m * 256 + c;
    __nv_bfloat16* pl = tokl + (size_t)m * 256 + c;
    float vv[4] = {v.x, v.y, v.z, v.w};
#pragma unroll
    for (int q = 0; q < 4; q++) {
        __nv_bfloat16 h = __float2bfloat16(vv[q]);
        ph[q] = h;
        pl[q] = __float2bfloat16(vv[q] - __bfloat162float(h));
    }
}

// ---------------- convert: two W's -> transposed split bf16 ----------------
__global__ void __launch_bounds__(256) convert_w_kernel(
        const float* __restrict__ Wa, const float* __restrict__ Wb,
        __nv_bfloat16* __restrict__ oh_base, __nv_bfloat16* __restrict__ ol_base) {
    const int elem = blockIdx.x * 1024 + threadIdx.x * 4;
    const int mat = elem >> 16;            // 0 or 1
    const int rem = elem & 65535;
    const int n = rem >> 8;
    const int k = rem & 255;
    const float* Wm = mat ? Wb : Wa;
    __nv_bfloat16* oh = oh_base + (size_t)mat * 65536 + (size_t)n * 256 + k;
    __nv_bfloat16* ol = ol_base + (size_t)mat * 65536 + (size_t)n * 256 + k;
#pragma unroll
    for (int q = 0; q < 4; q++) {
        float v = Wm[(size_t)(k + q) * 256 + n];
        __nv_bfloat16 h = __float2bfloat16(v);
        oh[q] = h;
        ol[q] = __float2bfloat16(v - __bfloat162float(h));
    }
}

// ---------------- KNN body (v6 logic, dynamic smem) ----------------
#define KCHUNK 1024
#define FULLM 0xffffffffu

#define KNN_EVENTS(e, v, iv, tau)                                          \
    {                                                                      \
        unsigned mm = __ballot_sync(FULLM, (e) < (tau));                   \
        while (mm) {                                                       \
            const int s = __ffs(mm) - 1; mm &= mm - 1;  /* ascending j */  \
            const float bd = __shfl_sync(FULLM, (e), s);                   \
            const int   bjj = jj - lane + s;                               \
            if (bd < (tau)) {  /* tau tightens within batch */             \
                const unsigned bal = __ballot_sync(FULLM, bd < (v));       \
                const int pp = __ffs(bal) - 1;                             \
                const float pv = __shfl_up_sync(FULLM, (v), 1);            \
                const int   pi = __shfl_up_sync(FULLM, (iv), 1);           \
                if (lane > pp)  { (v) = pv; (iv) = pi; }                   \
                if (lane == pp) { (v) = bd; (iv) = bjj; }                  \
                (tau) = __shfl_sync(FULLM, (v), 9);                        \
            }                                                              \
        }                                                                  \
    }

__device__ void knn_body(int bx, int b, const float* __restrict__ coords,
                         int* __restrict__ knn_out, float4* sp) {
    const float* coo = coords + (size_t)b * VOX * 3;
    const int warp = threadIdx.x >> 5;
    const int lane = threadIdx.x & 31;

    const int i0 = bx * 16 + warp * 2;
    const float x0 = coo[3*i0+0], y0 = coo[3*i0+1], z0 = coo[3*i0+2];
    const float x1 = coo[3*i0+3], y1 = coo[3*i0+4], z1 = coo[3*i0+5];
    const float sq0 = x0*x0 + y0*y0 + z0*z0;
    const float sq1 = x1*x1 + y1*y1 + z1*z1;

    float v0 = 1e30f, v1 = 1e30f;
    int  iv0 = 0x7fffffff, iv1 = 0x7fffffff;
    float tau0 = 1e30f, tau1 = 1e30f;

    for (int c = 0; c < VOX / KCHUNK; c++) {
        __syncthreads();
        for (int j = threadIdx.x; j < KCHUNK; j += 256) {
            const int jj = c * KCHUNK + j;
            const float xx = coo[3*jj], yy = coo[3*jj+1], zz = coo[3*jj+2];
            sp[j] = make_float4(xx, yy, zz, xx*xx + yy*yy + zz*zz);
        }
        __syncthreads();

        const int jbase = c * KCHUNK;
        for (int j = lane; j < KCHUNK; j += 32) {
            const float4 p = sp[j];
            const int jj = jbase + j;
            float e0 = sq0 + p.w - 2.0f*(x0*p.x + y0*p.y + z0*p.z);
            float e1 = sq1 + p.w - 2.0f*(x1*p.x + y1*p.y + z1*p.z);
            if (jj == i0)     e0 = 1e30f;
            if (jj == i0 + 1) e1 = 1e30f;
            KNN_EVENTS(e0, v0, iv0, tau0)
            KNN_EVENTS(e1, v1, iv1, tau1)
        }
    }

    if (lane < KNN_N) {
        knn_out[((b << 12) + i0 + 0) * KNN_N + lane] = iv0;
        knn_out[((b << 12) + i0 + 1) * KNN_N + lane] = iv1;
    }
}

// ---------------- fp32 GEMM body (selection path; dynamic smem) ----------------
__device__ void gemm_tile_f32(const float* __restrict__ A,
        const float* __restrict__ W, const float* __restrict__ bias,
        float* __restrict__ C, int N, int ldw, int m0, int n0, char* smem) {
    float* As = (float*)smem;        // [2][16][132]
    float* Bs = As + 2*16*132;       // [2][16][64]
#define ASX(buf,k,m) As[((buf)*16 + (k))*132 + (m)]
#define BSX(buf,k,n) Bs[((buf)*16 + (k))*64 + (n)]

    const int t  = threadIdx.x;
    const int tx = t & 15;
    const int ty = t >> 4;
    const int kq = (t & 3) * 4;
    const int ma = t >> 2;
    const int kb = t >> 4;
    const int nb = (t & 15) * 4;

    const float* Ab = A + (size_t)m0 * 256;

    float4 ra0 = *(const float4*)(Ab + (size_t)ma * 256 + kq);
    float4 ra1 = *(const float4*)(Ab + (size_t)(ma + 64) * 256 + kq);
    float4 rb  = *(const float4*)(W + (size_t)kb * ldw + n0 + nb);

    float acc[8][4];
#pragma unroll
    for (int i = 0; i < 8; i++)
#pragma unroll
        for (int j = 0; j < 4; j++) acc[i][j] = 0.0f;

    ASX(0,kq+0,ma) = ra0.x; ASX(0,kq+1,ma) = ra0.y; ASX(0,kq+2,ma) = ra0.z; ASX(0,kq+3,ma) = ra0.w;
    ASX(0,kq+0,ma+64) = ra1.x; ASX(0,kq+1,ma+64) = ra1.y; ASX(0,kq+2,ma+64) = ra1.z; ASX(0,kq+3,ma+64) = ra1.w;
    *(float4*)&BSX(0,kb,nb) = rb;
    __syncthreads();

    int cur = 0;
#pragma unroll
    for (int k0 = 0; k0 < 256; k0 += 16) {
        const bool more = (k0 + 16) < 256;
        if (more) {
            ra0 = *(const float4*)(Ab + (size_t)ma * 256 + k0 + 16 + kq);
            ra1 = *(const float4*)(Ab + (size_t)(ma + 64) * 256 + k0 + 16 + kq);
            rb  = *(const float4*)(W + (size_t)(k0 + 16 + kb) * ldw + n0 + nb);
        }
#pragma unroll
        for (int k = 0; k < 16; k++) {
            float ra[8], rbv[4];
            float4 a0 = *(const float4*)&ASX(cur,k,ty*8);
            float4 a1 = *(const float4*)&ASX(cur,k,ty*8+4);
            ra[0]=a0.x; ra[1]=a0.y; ra[2]=a0.z; ra[3]=a0.w;
            ra[4]=a1.x; ra[5]=a1.y; ra[6]=a1.z; ra[7]=a1.w;
            float4 b4 = *(const float4*)&BSX(cur,k,tx*4);
            rbv[0]=b4.x; rbv[1]=b4.y; rbv[2]=b4.z; rbv[3]=b4.w;
#pragma unroll
            for (int i = 0; i < 8; i++)
#pragma unroll
                for (int j = 0; j < 4; j++)
                    acc[i][j] += ra[i] * rbv[j];
        }
        if (more) {
            const int nx = cur ^ 1;
            ASX(nx,kq+0,ma) = ra0.x; ASX(nx,kq+1,ma) = ra0.y; ASX(nx,kq+2,ma) = ra0.z; ASX(nx,kq+3,ma) = ra0.w;
            ASX(nx,kq+0,ma+64) = ra1.x; ASX(nx,kq+1,ma+64) = ra1.y; ASX(nx,kq+2,ma+64) = ra1.z; ASX(nx,kq+3,ma+64) = ra1.w;
            *(float4*)&BSX(nx,kb,nb) = rb;
        }
        __syncthreads();
        cur ^= 1;
    }

    float4 bv = make_float4(0.f, 0.f, 0.f, 0.f);
    if (bias) bv = *(const float4*)(bias + n0 + tx*4);
#pragma unroll
    for (int i = 0; i < 8; i++) {
        const int row = m0 + ty*8 + i;
        float4 o;
        o.x = acc[i][0] + bv.x;
        o.y = acc[i][1] + bv.y;
        o.z = acc[i][2] + bv.z;
        o.w = acc[i][3] + bv.w;
        *(float4*)(C + (size_t)row * N + n0 + tx*4) = o;
    }
#undef ASX
#undef BSX
}

// ---------------- split-bf16 tensor-core GEMM (R11 v3, proven 115us shape) ----------------
__device__ __forceinline__ void mma_bf16(float* c, const uint32_t* a, const uint32_t* b) {
    asm volatile(
        "mma.sync.aligned.m16n8k16.row.col.f32.bf16.bf16.f32 "
        "{%0,%1,%2,%3}, {%4,%5,%6,%7}, {%8,%9}, {%0,%1,%2,%3};\n"
        : "+f"(c[0]), "+f"(c[1]), "+f"(c[2]), "+f"(c[3])
        : "r"(a[0]), "r"(a[1]), "r"(a[2]), "r"(a[3]), "r"(b[0]), "r"(b[1]));
}

#define ASTRIDE 40           // halves; 80B row stride -> conflict-free
#define TCBUF_H 15360        // halves per buffer: Ah 5120 | Al 5120 | Bh 2560 | Bl 2560
#define TC_SMEM_BYTES (2 * TCBUF_H * 2)   // 61440

__device__ void tc_gemm_tile_v3(
        const __nv_bfloat16* __restrict__ Ahi, const __nv_bfloat16* __restrict__ Alo,
        const __nv_bfloat16* __restrict__ Bth, const __nv_bfloat16* __restrict__ Btl,
        const float* __restrict__ bias, float* __restrict__ C, int m0, int n0,
        __nv_bfloat16* smem) {
    const int t    = threadIdx.x;
    const int warp = t >> 5;
    const int lane = t & 31;
    const int g    = lane >> 2;
    const int tg   = lane & 3;
    const int mw   = warp & 3;
    const int nw   = warp >> 2;

    const int ar = t >> 2;            // 0..63 (A rows ar, ar+64; B row ar)
    const int ao = (t & 3) * 8;       // 8-half segment

    const __nv_bfloat16* Ah_g = Ahi + (size_t)(m0 + ar) * 256 + ao;
    const __nv_bfloat16* Al_g = Alo + (size_t)(m0 + ar) * 256 + ao;
    const __nv_bfloat16* Bh_g = Bth + (size_t)(n0 + ar) * 256 + ao;
    const __nv_bfloat16* Bl_g = Btl + (size_t)(n0 + ar) * 256 + ao;

    const uint32_t smem_b = smem_u32(smem);
    const uint32_t dA0 = smem_b + (ar*ASTRIDE + ao)*2;
    const uint32_t dA1 = smem_b + ((ar+64)*ASTRIDE + ao)*2;
    const uint32_t dL0 = smem_b + (5120 + ar*ASTRIDE + ao)*2;
    const uint32_t dL1 = smem_b + (5120 + (ar+64)*ASTRIDE + ao)*2;
    const uint32_t dBh = smem_b + (10240 + ar*ASTRIDE + ao)*2;
    const uint32_t dBl = smem_b + (12800 + ar*ASTRIDE + ao)*2;

    float acc[2][4][4];
#pragma unroll
    for (int mt = 0; mt < 2; mt++)
#pragma unroll
        for (int nt = 0; nt < 4; nt++)
#pragma unroll
            for (int e = 0; e < 4; e++) acc[mt][nt][e] = 0.0f;

#define TC_ISSUE(buf, kk)                                                   \
    {                                                                       \
        const uint32_t bo_ = (buf) * (TCBUF_H * 2);                         \
        cp16(dA0 + bo_, Ah_g + (kk));                                       \
        cp16(dA1 + bo_, Ah_g + (size_t)64*256 + (kk));                      \
        cp16(dL0 + bo_, Al_g + (kk));                                       \
        cp16(dL1 + bo_, Al_g + (size_t)64*256 + (kk));                      \
        cp16(dBh + bo_, Bh_g + (kk));                                       \
        cp16(dBl + bo_, Bl_g + (kk));                                       \
        cp_commit();                                                        \
    }

    TC_ISSUE(0, 0)
    int cur = 0;

#pragma unroll
    for (int k0 = 0; k0 < 256; k0 += 32) {
        const bool more = (k0 + 32) < 256;
        if (more) { TC_ISSUE(cur ^ 1, k0 + 32) cp_wait<1>(); }
        else      { cp_wait<0>(); }
        __syncthreads();

        const __nv_bfloat16* Ah = smem + cur * TCBUF_H;
        const __nv_bfloat16* Al = Ah + 5120;
        const __nv_bfloat16* Bh = Ah + 10240;
        const __nv_bfloat16* Bl = Ah + 12800;

#pragma unroll
        for (int ks = 0; ks < 32; ks += 16) {
            uint32_t ah[2][4], al[2][4];
#pragma unroll
            for (int mt = 0; mt < 2; mt++) {
                const int r = mw*32 + mt*16 + g;
                ah[mt][0] = *(const uint32_t*)&Ah[r*ASTRIDE + ks + 2*tg];
                ah[mt][1] = *(const uint32_t*)&Ah[(r+8)*ASTRIDE + ks + 2*tg];
                ah[mt][2] = *(const uint32_t*)&Ah[r*ASTRIDE + ks + 8 + 2*tg];
                ah[mt][3] = *(const uint32_t*)&Ah[(r+8)*ASTRIDE + ks + 8 + 2*tg];
                al[mt][0] = *(const uint32_t*)&Al[r*ASTRIDE + ks + 2*tg];
                al[mt][1] = *(const uint32_t*)&Al[(r+8)*ASTRIDE + ks + 2*tg];
                al[mt][2] = *(const uint32_t*)&Al[r*ASTRIDE + ks + 8 + 2*tg];
                al[mt][3] = *(const uint32_t*)&Al[(r+8)*ASTRIDE + ks + 8 + 2*tg];
            }
            uint32_t bh[4][2], bl[4][2];
#pragma unroll
            for (int nt = 0; nt < 4; nt++) {
                const int n = nw*32 + nt*8 + g;
                bh[nt][0] = *(const uint32_t*)&Bh[n*ASTRIDE + ks + 2*tg];
                bh[nt][1] = *(const uint32_t*)&Bh[n*ASTRIDE + ks + 8 + 2*tg];
                bl[nt][0] = *(const uint32_t*)&Bl[n*ASTRIDE + ks + 2*tg];
                bl[nt][1] = *(const uint32_t*)&Bl[n*ASTRIDE + ks + 8 + 2*tg];
            }
#pragma unroll
            for (int mt = 0; mt < 2; mt++)
#pragma unroll
                for (int nt = 0; nt < 4; nt++) {
                    mma_bf16(acc[mt][nt], ah[mt], bh[nt]);
                    mma_bf16(acc[mt][nt], ah[mt], bl[nt]);
                    mma_bf16(acc[mt][nt], al[mt], bh[nt]);
                }
        }
        __syncthreads();
        cur ^= 1;
    }
#undef TC_ISSUE

#pragma unroll
    for (int nt = 0; nt < 4; nt++) {
        const int c = n0 + nw*32 + nt*8 + 2*tg;
        float bx = 0.f, by = 0.f;
        if (bias) { bx = bias[c]; by = bias[c+1]; }
#pragma unroll
        for (int mt = 0; mt < 2; mt++) {
            const int r = m0 + mw*32 + mt*16 + g;
            float* Cp = C + (size_t)r * 256 + c;
            Cp[0] = acc[mt][nt][0] + bx;
            Cp[1] = acc[mt][nt][1] + by;
            Cp[(size_t)8*256]     = acc[mt][nt][2] + bx;
            Cp[(size_t)8*256 + 1] = acc[mt][nt][3] + by;
        }
    }
}

// ---------------- mega2: knn (1024) + QKV (1536) + AB (256) ----------------
__global__ void __launch_bounds__(256, 3) mega2_kernel(
        const float* __restrict__ coords, int* __restrict__ knn_out,
        const __nv_bfloat16* __restrict__ tokh, const __nv_bfloat16* __restrict__ tokl,
        const __nv_bfloat16* __restrict__ wth,  const __nv_bfloat16* __restrict__ wtl,
        const float* __restrict__ bq, const float* __restrict__ bk, const float* __restrict__ bv,
        float* __restrict__ gQ, float* __restrict__ gK, float* __restrict__ gV,
        const float* __restrict__ tok, const float* __restrict__ W1,
        const float* __restrict__ b1, float* __restrict__ gA, float* __restrict__ gB) {
    extern __shared__ __align__(16) char dynsmem[];
    const int bid = blockIdx.x;
    if (bid < 1024) {
        // knn: long pole, dispatched first (alu/issue pipe; complements tc)
        knn_body(bid & 255, bid >> 8, coords, knn_out, (float4*)dynsmem);
    } else if (bid < 2560) {
        const int q = bid - 1024;
        const int z = q / 512;
        const int r = q % 512;
        const float* bias = (z == 0) ? bq : (z == 1) ? bk : bv;
        float*       C    = (z == 0) ? gQ : (z == 1) ? gK : gV;
        tc_gemm_tile_v3(tokh, tokl, wth + (size_t)z * 65536, wtl + (size_t)z * 65536,
                        bias, C, (r & 127) * 128, (r >> 7) * 64,
                        (__nv_bfloat16*)dynsmem);
    } else {
        const int a = bid - 2560;           // 0..255
        const int z = a >> 7;               // 0 -> A, 1 -> B
        const float* W    = z ? (W1 + 256*HIDN) : W1;
        const float* bias = z ? nullptr : b1;
        float*       C    = z ? gB : gA;
        gemm_tile_f32(tok, W, bias, C, HIDN, HIDN, (a & 127) * 128, 0, dynsmem);
    }
}

// ---------------- O projection ----------------
__global__ void __launch_bounds__(256, 3) tc_o_kernel(
        const __nv_bfloat16* __restrict__ ctxh, const __nv_bfloat16* __restrict__ ctxl,
        const __nv_bfloat16* __restrict__ wth,  const __nv_bfloat16* __restrict__ wtl,
        const float* __restrict__ bo, float* __restrict__ out) {
    extern __shared__ __align__(16) char dynsmem[];
    tc_gemm_tile_v3(ctxh, ctxl, wth + (size_t)3 * 65536, wtl + (size_t)3 * 65536,
                    bo, out, blockIdx.x * 128, blockIdx.y * 64,
                    (__nv_bfloat16*)dynsmem);
}

// ---------------- fused score + top-4 select + attention ----------------
__global__ void score_attn_kernel(const float* __restrict__ coords,
                                  const float* __restrict__ W1,
                                  const float* __restrict__ W2,
                                  const int* __restrict__ knn,
                                  const float* __restrict__ gA,
                                  const float* __restrict__ gB,
                                  const float* __restrict__ gQ,
                                  const float* __restrict__ gK,
                                  const float* __restrict__ gV,
                                  __nv_bfloat16* __restrict__ ctxh,
                                  __nv_bfloat16* __restrict__ ctxl) {
    __shared__ float sW1c[3][64];
    __shared__ float sW2[64];
    const int t = threadIdx.x;
    if (t < 64) {
        sW2[t]     = W2[t];
        sW1c[0][t] = W1[512*64 + t];
        sW1c[1][t] = W1[513*64 + t];
        sW1c[2][t] = W1[514*64 + t];
    }
    __syncthreads();

    const int warp = t >> 5, lane = t & 31;
    const int g = blockIdx.x * 8 + warp;
    const int b = g >> 12;
    const int i = g & 4095;
    const float* coo = coords + (size_t)b * VOX * 3;
    const float xi = coo[3*i+0], yi = coo[3*i+1], zi = coo[3*i+2];

    const float a0  = gA[(size_t)g*64 + lane];
    const float a1  = gA[(size_t)g*64 + lane + 32];
    const float w2a = sW2[lane], w2b = sW2[lane + 32];
    const float c0a = sW1c[0][lane], c0b = sW1c[0][lane+32];
    const float c1a = sW1c[1][lane], c1b = sW1c[1][lane+32];
    const float c2a = sW1c[2][lane], c2b = sW1c[2][lane+32];

    float bs[TOPK_N] = {-1e30f, -1e30f, -1e30f, -1e30f};
    int   bj[TOPK_N] = {0, 0, 0, 0};

#pragma unroll
    for (int nb = 0; nb < KNN_N; nb++) {
        const int j = knn[g*KNN_N + nb];
        const float rx = coo[3*j+0] - xi;
        const float ry = coo[3*j+1] - yi;
        const float rz = coo[3*j+2] - zi;
        const float* Bj = gB + ((size_t)(b << 12) + j) * 64;
        float h0 = a0 + Bj[lane]      + rx*c0a + ry*c1a + rz*c2a;
        float h1 = a1 + Bj[lane + 32] + rx*c0b + ry*c1b + rz*c2b;
        h0 = fmaxf(h0, 0.0f);
        h1 = fmaxf(h1, 0.0f);
        float p = h0 * w2a + h1 * w2b;
#pragma unroll
        for (int off = 16; off; off >>= 1) p += __shfl_xor_sync(0xffffffffu, p, off);
        float cs = p; int cj = j;
#pragma unroll
        for (int k = 0; k < TOPK_N; k++) {
            const bool better = cs > bs[k];
            const float ts = better ? bs[k] : cs;
            const int   tj = better ? bj[k] : cj;
            bs[k] = better ? cs : bs[k];
            bj[k] = better ? cj : bj[k];
            cs = ts; cj = tj;
        }
    }

    const size_t base = (size_t)g * DIM + lane * 8;
    const float4 q0 = *(const float4*)(gQ + base);
    const float4 q1 = *(const float4*)(gQ + base + 4);

    float att[TOPK_N];
#pragma unroll
    for (int s = 0; s < TOPK_N; s++) {
        const size_t jb = ((size_t)(b << 12) + bj[s]) * DIM + lane * 8;
        const float4* Kp = (const float4*)(gK + jb);
        const float4 k0 = Kp[0], k1 = Kp[1];
        float p = q0.x*k0.x + q0.y*k0.y + q0.z*k0.z + q0.w*k0.w
                + q1.x*k1.x + q1.y*k1.y + q1.z*k1.z + q1.w*k1.w;
        p += __shfl_xor_sync(0xffffffffu, p, 4);
        p += __shfl_xor_sync(0xffffffffu, p, 2);
        p += __shfl_xor_sync(0xffffffffu, p, 1);
        att[s] = p * 0.125f;
    }
    float m = fmaxf(fmaxf(att[0], att[1]), fmaxf(att[2], att[3]));
    float e[TOPK_N], ssum = 0.0f;
#pragma unroll
    for (int s = 0; s < TOPK_N; s++) { e[s] = expf(att[s] - m); ssum += e[s]; }
    const float inv = 1.0f / ssum;

    float cv[8] = {0.f,0.f,0.f,0.f,0.f,0.f,0.f,0.f};
#pragma unroll
    for (int s = 0; s < TOPK_N; s++) {
        const float w = e[s] * inv;
        const size_t jb = ((size_t)(b << 12) + bj[s]) * DIM + lane * 8;
        const float4* Vp = (const float4*)(gV + jb);
        const float4 v0 = Vp[0], v1 = Vp[1];
        cv[0] += w*v0.x; cv[1] += w*v0.y; cv[2] += w*v0.z; cv[3] += w*v0.w;
        cv[4] += w*v1.x; cv[5] += w*v1.y; cv[6] += w*v1.z; cv[7] += w*v1.w;
    }
    uint32_t uh[4], ul[4];
#pragma unroll
    for (int q = 0; q < 4; q++) {
        __nv_bfloat16 h0 = __float2bfloat16(cv[2*q]);
        __nv_bfloat16 h1 = __float2bfloat16(cv[2*q+1]);
        __nv_bfloat16 l0 = __float2bfloat16(cv[2*q]   - __bfloat162float(h0));
        __nv_bfloat16 l1 = __float2bfloat16(cv[2*q+1] - __bfloat162float(h1));
        __nv_bfloat162 ph(h0, h1), pl(l0, l1);
        uh[q] = *(uint32_t*)&ph;
        ul[q] = *(uint32_t*)&pl;
    }
    *(uint4*)(ctxh + base) = make_uint4(uh[0], uh[1], uh[2], uh[3]);
    *(uint4*)(ctxl + base) = make_uint4(ul[0], ul[1], ul[2], ul[3]);
}

// ---------------- launch ----------------
extern "C" void kernel_launch(void* const* d_in, const int* in_sizes, int n_in,
                              void* d_out, int out_size) {
    const float* tok    = (const float*)d_in[0];
    const float* coords = (const float*)d_in[1];
    const float* W1 = (const float*)d_in[3];
    const float* b1 = (const float*)d_in[4];
    const float* W2 = (const float*)d_in[5];
    const float* Wq = (const float*)d_in[7];
    const float* bq = (const float*)d_in[8];
    const float* Wk = (const float*)d_in[9];
    const float* bk = (const float*)d_in[10];
    const float* Wv = (const float*)d_in[11];
    const float* bv = (const float*)d_in[12];
    const float* Wo = (const float*)d_in[13];
    const float* bo = (const float*)d_in[14];
    float* out = (float*)d_out;

    void* bufp = nullptr;
    cudaGetSymbolAddress(&bufp, g_buf);
    float* buf = (float*)bufp;
    float* gA   = buf + OFF_A;
    float* gB   = buf + OFF_B;
    float* gQ   = buf + OFF_Q;
    float* gK   = buf + OFF_K;
    float* gV   = buf + OFF_V;
    int*   gknn = (int*)(buf + OFF_KNN);
    __nv_bfloat16* ctxh = (__nv_bfloat16*)(buf + OFF_CTXH);
    __nv_bfloat16* ctxl = (__nv_bfloat16*)(buf + OFF_CTXL);
    __nv_bfloat16* tokh = (__nv_bfloat16*)(buf + OFF_TOKH);
    __nv_bfloat16* tokl = (__nv_bfloat16*)(buf + OFF_TOKL);
    __nv_bfloat16* wth  = (__nv_bfloat16*)(buf + OFF_WTH);
    __nv_bfloat16* wtl  = (__nv_bfloat16*)(buf + OFF_WTL);

    cudaFuncSetAttribute(mega2_kernel, cudaFuncAttributeMaxDynamicSharedMemorySize, TC_SMEM_BYTES);
    cudaFuncSetAttribute(tc_o_kernel,  cudaFuncAttributeMaxDynamicSharedMemorySize, TC_SMEM_BYTES);

    // #0..#2: split-convert
    convert_tok_kernel<<<4096, 256>>>(tok, tokh, tokl);
    convert_w_kernel<<<128, 256>>>(Wq, Wk, wth, wtl);
    convert_w_kernel<<<128, 256>>>(Wv, Wo, wth + 2*65536, wtl + 2*65536);
    // #3: mega2 — knn + QKV + AB co-resident (matched footprints)  <-- ncu slot
    mega2_kernel<<<2816, 256, TC_SMEM_BYTES>>>(coords, gknn, tokh, tokl, wth, wtl,
                                               bq, bk, bv, gQ, gK, gV,
                                               tok, W1, b1, gA, gB);
    // #4: fused score + select + attention (writes split ctx)
    score_attn_kernel<<<GTOT/8, 256>>>(coords, W1, W2, gknn, gA, gB, gQ, gK, gV, ctxh, ctxl);
    // #5: output projection
    tc_o_kernel<<<dim3(GTOT/128, DIM/64), 256, TC_SMEM_BYTES>>>(ctxh, ctxl, wth, wtl, bo, out);
}